// round 5
// baseline (speedup 1.0000x reference)
#include <cuda_runtime.h>
#include <cuda_bf16.h>
#include <cstddef>

#define E_TOT 512
#define Dd    64
#define Hh    256
#define Nn    16
#define Aa    8
#define Tt    128
#define RPB   4                // MLP rows per block -> 128 blocks
#define HO    (Nn + Aa * Nn)   // 144 head outputs

#define SF2   0.01f
#define SN2   0.01f
#define NEG_HALF_INV_L2 (-50.0f)   // -0.5 / 0.1^2

// scratch (no allocation allowed -> device globals)
__device__ float g_times[E_TOT * Nn];
__device__ float g_anchors[E_TOT * Aa * Nn];
__device__ float g_WT1[Dd * Hh];    // W1^T : [64][256]
__device__ float g_WT2[Hh * Hh];    // W2^T : [256][256]
__device__ float g_WhT[Hh * HO];    // [Wt;Wa]^T : [256][144]

// ---------------------------------------------------------------------------
// Kernel 0: smem-tile transpose of all weights (coalesced both directions).
// Tile grid: W1 8x2=16, W2 8x8=64, Wh 5x8=40  -> 120 blocks, 32x8 threads.
// ---------------------------------------------------------------------------
__global__ __launch_bounds__(256)
void prep_kernel(const float* __restrict__ W1, const float* __restrict__ W2,
                 const float* __restrict__ Wt, const float* __restrict__ Wa)
{
    __shared__ float tile[32][33];
    const int tx = threadIdx.x & 31;
    const int ty = threadIdx.x >> 5;      // 0..7
    int b = blockIdx.x;

    const float* src; float* dst;
    int rows, cols, br, bc;               // src is [rows][cols]
    if (b < 16) {                         // W1: [256][64] -> g_WT1 [64][256]
        src = W1; dst = g_WT1; rows = Hh; cols = Dd;
        br = b >> 1; bc = b & 1;
    } else if (b < 80) {                  // W2: [256][256] -> g_WT2
        b -= 16;
        src = W2; dst = g_WT2; rows = Hh; cols = Hh;
        br = b >> 3; bc = b & 7;
    } else {                              // Wh: [144][256] -> g_WhT [256][144]
        b -= 80;
        src = nullptr; dst = g_WhT; rows = HO; cols = Hh;
        br = b / 8; bc = b % 8;
    }

    const int r0 = br * 32, c0 = bc * 32;
    #pragma unroll
    for (int rr = 0; rr < 4; rr++) {
        int r = r0 + ty + rr * 8;
        if (r < rows) {
            float v;
            if (src) v = src[r * cols + c0 + tx];
            else     v = (r < Nn) ? Wt[r * Hh + c0 + tx] : Wa[(r - Nn) * Hh + c0 + tx];
            tile[ty + rr * 8][tx] = v;
        }
    }
    __syncthreads();
    #pragma unroll
    for (int rr = 0; rr < 4; rr++) {
        int c = c0 + ty + rr * 8;           // output row = src col
        int o = r0 + tx;                    // output col = src row
        if (o < rows)                       // (c always < cols)
            dst[c * rows + o] = tile[tx][ty + rr * 8];
    }
}

// ---------------------------------------------------------------------------
// Kernel 1: MLP. 128 blocks x 4 rows, 256 threads. thread = output column,
// weights read coalesced from transposed scratch, activations via smem bcast.
// ---------------------------------------------------------------------------
__global__ __launch_bounds__(256)
void mlp_kernel(const float* __restrict__ x,
                const float* __restrict__ b1, const float* __restrict__ b2,
                const float* __restrict__ bt, const float* __restrict__ ba)
{
    __shared__ float xs [RPB][Dd];
    __shared__ float h1s[RPB][Hh];
    __shared__ float h2s[RPB][Hh];

    const int tid = threadIdx.x;
    const int e0  = blockIdx.x * RPB;

    // RPB*Dd == 256: one element per thread, coalesced
    xs[tid >> 6][tid & 63] = x[e0 * Dd + tid];
    __syncthreads();

    // ---- layer 1 ----
    {
        float acc[RPB];
        float bias = b1[tid];
        #pragma unroll
        for (int r = 0; r < RPB; r++) acc[r] = bias;
        #pragma unroll 4
        for (int k = 0; k < Dd; k += 4) {
            float w0 = g_WT1[(k + 0) * Hh + tid];
            float w1 = g_WT1[(k + 1) * Hh + tid];
            float w2 = g_WT1[(k + 2) * Hh + tid];
            float w3 = g_WT1[(k + 3) * Hh + tid];
            #pragma unroll
            for (int r = 0; r < RPB; r++) {
                float4 v = *(const float4*)&xs[r][k];
                acc[r] += w0 * v.x + w1 * v.y + w2 * v.z + w3 * v.w;
            }
        }
        #pragma unroll
        for (int r = 0; r < RPB; r++) h1s[r][tid] = tanhf(acc[r]);
    }
    __syncthreads();

    // ---- layer 2 ----
    {
        float acc[RPB];
        float bias = b2[tid];
        #pragma unroll
        for (int r = 0; r < RPB; r++) acc[r] = bias;
        #pragma unroll 8
        for (int k = 0; k < Hh; k += 4) {
            float w0 = g_WT2[(k + 0) * Hh + tid];
            float w1 = g_WT2[(k + 1) * Hh + tid];
            float w2 = g_WT2[(k + 2) * Hh + tid];
            float w3 = g_WT2[(k + 3) * Hh + tid];
            #pragma unroll
            for (int r = 0; r < RPB; r++) {
                float4 v = *(const float4*)&h1s[r][k];
                acc[r] += w0 * v.x + w1 * v.y + w2 * v.z + w3 * v.w;
            }
        }
        #pragma unroll
        for (int r = 0; r < RPB; r++) h2s[r][tid] = tanhf(acc[r]);
    }
    __syncthreads();

    // ---- heads (144 outputs, threads 0..143) ----
    if (tid < HO) {
        float acc[RPB];
        float bias = (tid < Nn) ? bt[tid] : ba[tid - Nn];
        #pragma unroll
        for (int r = 0; r < RPB; r++) acc[r] = bias;
        #pragma unroll 8
        for (int k = 0; k < Hh; k += 4) {
            float w0 = g_WhT[(k + 0) * HO + tid];
            float w1 = g_WhT[(k + 1) * HO + tid];
            float w2 = g_WhT[(k + 2) * HO + tid];
            float w3 = g_WhT[(k + 3) * HO + tid];
            #pragma unroll
            for (int r = 0; r < RPB; r++) {
                float4 v = *(const float4*)&h2s[r][k];
                acc[r] += w0 * v.x + w1 * v.y + w2 * v.z + w3 * v.w;
            }
        }
        if (tid < Nn) {
            #pragma unroll
            for (int r = 0; r < RPB; r++) g_times[(e0 + r) * Nn + tid] = acc[r];
        } else {
            #pragma unroll
            for (int r = 0; r < RPB; r++) g_anchors[(e0 + r) * (Aa * Nn) + (tid - Nn)] = acc[r];
        }
    }
}

// ---------------------------------------------------------------------------
// Kernel 2: GP per environment e. 512 blocks, 256 threads.  (R1 exact)
// ---------------------------------------------------------------------------
__global__ __launch_bounds__(256)
void gp_kernel(const float* __restrict__ tq_g,
               float* __restrict__ out_mu,
               float* __restrict__ out_cov)
{
    __shared__ float tq[Tt];
    __shared__ float kssd[Tt];               // Kss[i][j] == kssd[|i-j|]
    __shared__ float tt[Nn];
    __shared__ float ys[Aa][Nn];
    __shared__ float Aug[Nn][2 * Nn + 1];    // [K | I] -> [I | K^-1], pad 33
    __shared__ float colk[Nn];
    __shared__ float St[Nn][Tt + 4];         // Ks transposed: St[n][j], pad 132
    __shared__ float U[Tt][Nn + 1];          // U = Ks @ K^-1, pad 17

    const int e   = blockIdx.x;
    const int tid = threadIdx.x;

    if (tid < Tt) tq[tid] = tq_g[tid];
    if (tid < Nn) tt[tid] = g_times[e * Nn + tid];
    if (tid >= 128 && tid < 128 + Aa * Nn) {
        int q = tid - 128;
        ys[q >> 4][q & 15] = g_anchors[e * (Aa * Nn) + q];
    }
    __syncthreads();

    if (tid < Tt) {
        float d = tq[tid] - tq[0];
        kssd[tid] = SF2 * __expf(NEG_HALF_INV_L2 * d * d);
    }
    // build [K + sn2 I | I]  (exactly 256 entries of K)
    {
        int i = tid >> 4, j = tid & 15;
        float d = tt[i] - tt[j];
        float v = SF2 * __expf(NEG_HALF_INV_L2 * d * d);
        if (i == j) v += SN2;
        Aug[i][j] = v;
        Aug[i][Nn + j] = (i == j) ? 1.0f : 0.0f;
    }
    __syncthreads();

    // Gauss-Jordan (SPD, no pivoting needed, cond(K) <= 17)
    for (int k = 0; k < Nn; k++) {
        float pinv = 1.0f / Aug[k][k];
        __syncthreads();
        if (tid < 32) Aug[k][tid] *= pinv;
        if (tid >= 32 && tid < 48) colk[tid - 32] = Aug[tid - 32][k];
        __syncthreads();
        {
            int idx = tid;            // 512 elements, 256 threads, 2 each
            int i0 = idx >> 5, j0 = idx & 31;
            if (i0 != k) Aug[i0][j0] -= colk[i0] * Aug[k][j0];
            idx += 256;
            int i1 = idx >> 5, j1 = idx & 31;
            if (i1 != k) Aug[i1][j1] -= colk[i1] * Aug[k][j1];
        }
        __syncthreads();
    }

    // Ks transposed: St[n][j] = sf2 * exp(-0.5 (tq[j]-t[n])^2 / l2)
    for (int idx = tid; idx < Tt * Nn; idx += 256) {
        int j = idx >> 4, n = idx & 15;
        float d = tq[j] - tt[n];
        St[n][j] = SF2 * __expf(NEG_HALF_INV_L2 * d * d);
    }
    __syncthreads();

    // U[i][n] = sum_m Ks[i][m] * Kinv[m][n]
    for (int idx = tid; idx < Tt * Nn; idx += 256) {
        int i = idx >> 4, n = idx & 15;
        float s = 0.0f;
        #pragma unroll
        for (int m = 0; m < Nn; m++) s += St[m][i] * Aug[m][Nn + n];
        U[i][n] = s;
    }
    __syncthreads();

    // mu[a][i] = sum_n U[i][n] * y[a][n]
    for (int idx = tid; idx < Aa * Tt; idx += 256) {
        int a = idx >> 7, i = idx & 127;
        float s = 0.0f;
        #pragma unroll
        for (int n = 0; n < Nn; n++) s += U[i][n] * ys[a][n];
        out_mu[((size_t)e * Aa + a) * Tt + i] = s;
    }

    // cov[i][j] = kssd[|i-j|] - dot16(U[i], Ks[j]); written 8x (one per anchor)
    const int lane = tid & 31;
    const int grp  = tid >> 5;
    const int j0   = lane * 4;
    for (int step = 0; step < Tt / 8; step++) {
        int i = step * 8 + grp;
        float u[Nn];
        #pragma unroll
        for (int n = 0; n < Nn; n++) u[n] = U[i][n];   // broadcast LDS
        float a0 = 0.f, a1 = 0.f, a2 = 0.f, a3 = 0.f;
        #pragma unroll
        for (int n = 0; n < Nn; n++) {
            float4 s4 = *(const float4*)&St[n][j0];    // conflict-free LDS.128
            float un = u[n];
            a0 += un * s4.x; a1 += un * s4.y; a2 += un * s4.z; a3 += un * s4.w;
        }
        int d0 = i - j0;       d0 = d0 < 0 ? -d0 : d0;
        int d1 = i - (j0 + 1); d1 = d1 < 0 ? -d1 : d1;
        int d2 = i - (j0 + 2); d2 = d2 < 0 ? -d2 : d2;
        int d3 = i - (j0 + 3); d3 = d3 < 0 ? -d3 : d3;
        float4 v;
        v.x = kssd[d0] - a0;
        v.y = kssd[d1] - a1;
        v.z = kssd[d2] - a2;
        v.w = kssd[d3] - a3;
        size_t base = (((size_t)e * Aa) * Tt + i) * Tt + j0;
        #pragma unroll
        for (int a = 0; a < Aa; a++) {
            *(float4*)&out_cov[base + (size_t)a * Tt * Tt] = v;   // coalesced STG.128
        }
    }
}

// ---------------------------------------------------------------------------
extern "C" void kernel_launch(void* const* d_in, const int* in_sizes, int n_in,
                              void* d_out, int out_size)
{
    const float* x  = (const float*)d_in[0];
    // d_in[1] = a, d_in[2] = da (unused by reference)
    const float* W1 = (const float*)d_in[3];
    const float* b1 = (const float*)d_in[4];
    const float* W2 = (const float*)d_in[5];
    const float* b2 = (const float*)d_in[6];
    const float* Wt = (const float*)d_in[7];
    const float* bt = (const float*)d_in[8];
    const float* Wa = (const float*)d_in[9];
    const float* ba = (const float*)d_in[10];
    const float* tq = (const float*)d_in[11];

    float* out     = (float*)d_out;
    float* out_mu  = out;                                   // E*A*T floats
    float* out_cov = out + (size_t)E_TOT * Aa * Tt;         // E*A*T*T floats

    prep_kernel<<<120, 256>>>(W1, W2, Wt, Wa);
    mlp_kernel<<<E_TOT / RPB, 256>>>(x, b1, b2, bt, ba);
    gp_kernel<<<E_TOT, 256>>>(tq, out_mu, out_cov);
}

// round 6
// speedup vs baseline: 1.0316x; 1.0316x over previous
#include <cuda_runtime.h>
#include <cuda_bf16.h>
#include <cstddef>

#define E_TOT 512
#define Dd    64
#define Hh    256
#define Nn    16
#define Aa    8
#define Tt    128
#define HO    (Nn + Aa * Nn)   // 144 head outputs

#define SF2   0.01f
#define SN2   0.01f
#define NEG_HALF_INV_L2 (-50.0f)   // -0.5 / 0.1^2

// scratch (no allocation allowed -> device globals)
__device__ float g_h1[E_TOT * Hh];     // layer-1 activations
__device__ float g_h2[E_TOT * Hh];     // layer-2 activations
__device__ float g_head[E_TOT * HO];   // [times(16) | anchors(128)] per e

// ---------------------------------------------------------------------------
// Tiled GEMM: C[row][col] = act( A[row][:] . W[col][:] + bias[col] )
//   A: [E][KTOT] row-major.  W: [OUTC][KTOT] row-major (SPLITW: rows<16 from
//   Wt, rest from Wa).  Micro-kernel 2 rows x 4 cols per thread.
//   Both operands staged to smem transposed ([k][row/col]) with padding so the
//   inner k-loop is conflict-free LDS + FFMA only.
// ---------------------------------------------------------------------------
template<int BM, int BN, int NT, int KTOT, bool DOTANH, bool SPLITW>
__global__ __launch_bounds__(NT)
void gemm_kernel(const float* __restrict__ A,
                 const float* __restrict__ W,   // or Wt when SPLITW
                 const float* __restrict__ Wb,  // Wa when SPLITW (else unused)
                 const float* __restrict__ bias,   // or bt
                 const float* __restrict__ biasb,  // ba when SPLITW
                 float* __restrict__ C, int OUTC)
{
    __shared__ float Ash[64][BM + 2];   // even stride: 8B-aligned pairs
    __shared__ float Bsh[64][BN + 1];

    const int tid  = threadIdx.x;
    const int ty   = tid & 15;          // row group 0..15
    const int tx   = tid >> 4;          // col group
    const int row0 = blockIdx.x * BM;
    const int col0 = blockIdx.y * BN;

    float acc[2][4] = {{0.f,0.f,0.f,0.f},{0.f,0.f,0.f,0.f}};

    for (int k0 = 0; k0 < KTOT; k0 += 64) {
        // stage A tile (coalesced: kk fast within contiguous rows)
        for (int i = tid; i < BM * 64; i += NT) {
            int r = i >> 6, kk = i & 63;
            Ash[kk][r] = A[(row0 + r) * KTOT + k0 + kk];
        }
        // stage W tile
        for (int i = tid; i < BN * 64; i += NT) {
            int c = i >> 6, kk = i & 63;
            int cg = col0 + c;
            float v;
            if (SPLITW) v = (cg < Nn) ? W[cg * KTOT + k0 + kk]
                                      : Wb[(cg - Nn) * KTOT + k0 + kk];
            else        v = W[cg * KTOT + k0 + kk];
            Bsh[kk][c] = v;
        }
        __syncthreads();

        #pragma unroll 8
        for (int kk = 0; kk < 64; kk++) {
            float a0 = Ash[kk][ty * 2 + 0];
            float a1 = Ash[kk][ty * 2 + 1];
            float b0 = Bsh[kk][tx * 4 + 0];
            float b1 = Bsh[kk][tx * 4 + 1];
            float b2 = Bsh[kk][tx * 4 + 2];
            float b3 = Bsh[kk][tx * 4 + 3];
            acc[0][0] += a0 * b0; acc[0][1] += a0 * b1;
            acc[0][2] += a0 * b2; acc[0][3] += a0 * b3;
            acc[1][0] += a1 * b0; acc[1][1] += a1 * b1;
            acc[1][2] += a1 * b2; acc[1][3] += a1 * b3;
        }
        __syncthreads();
    }

    #pragma unroll
    for (int r = 0; r < 2; r++) {
        int row = row0 + ty * 2 + r;
        #pragma unroll
        for (int j = 0; j < 4; j++) {
            int col = col0 + tx * 4 + j;
            float bv;
            if (SPLITW) bv = (col < Nn) ? bias[col] : biasb[col - Nn];
            else        bv = bias[col];
            float v = acc[r][j] + bv;
            if (DOTANH) v = tanhf(v);
            C[row * OUTC + col] = v;
        }
    }
}

// ---------------------------------------------------------------------------
// GP per environment e. 512 blocks, 256 threads.  (R1 exact, proven 50.9us;
// only the times/anchors source addresses changed to g_head.)
// ---------------------------------------------------------------------------
__global__ __launch_bounds__(256)
void gp_kernel(const float* __restrict__ tq_g,
               float* __restrict__ out_mu,
               float* __restrict__ out_cov)
{
    __shared__ float tq[Tt];
    __shared__ float kssd[Tt];               // Kss[i][j] == kssd[|i-j|]
    __shared__ float tt[Nn];
    __shared__ float ys[Aa][Nn];
    __shared__ float Aug[Nn][2 * Nn + 1];    // [K | I] -> [I | K^-1], pad 33
    __shared__ float colk[Nn];
    __shared__ float St[Nn][Tt + 4];         // Ks transposed: St[n][j], pad 132
    __shared__ float U[Tt][Nn + 1];          // U = Ks @ K^-1, pad 17

    const int e   = blockIdx.x;
    const int tid = threadIdx.x;

    if (tid < Tt) tq[tid] = tq_g[tid];
    if (tid < Nn) tt[tid] = g_head[e * HO + tid];
    if (tid >= 128 && tid < 128 + Aa * Nn) {
        int q = tid - 128;
        ys[q >> 4][q & 15] = g_head[e * HO + Nn + q];
    }
    __syncthreads();

    if (tid < Tt) {
        float d = tq[tid] - tq[0];
        kssd[tid] = SF2 * __expf(NEG_HALF_INV_L2 * d * d);
    }
    // build [K + sn2 I | I]  (exactly 256 entries of K)
    {
        int i = tid >> 4, j = tid & 15;
        float d = tt[i] - tt[j];
        float v = SF2 * __expf(NEG_HALF_INV_L2 * d * d);
        if (i == j) v += SN2;
        Aug[i][j] = v;
        Aug[i][Nn + j] = (i == j) ? 1.0f : 0.0f;
    }
    __syncthreads();

    // Gauss-Jordan (SPD, no pivoting needed, cond(K) <= 17)
    for (int k = 0; k < Nn; k++) {
        float pinv = 1.0f / Aug[k][k];
        __syncthreads();
        if (tid < 32) Aug[k][tid] *= pinv;
        if (tid >= 32 && tid < 48) colk[tid - 32] = Aug[tid - 32][k];
        __syncthreads();
        {
            int idx = tid;            // 512 elements, 256 threads, 2 each
            int i0 = idx >> 5, j0 = idx & 31;
            if (i0 != k) Aug[i0][j0] -= colk[i0] * Aug[k][j0];
            idx += 256;
            int i1 = idx >> 5, j1 = idx & 31;
            if (i1 != k) Aug[i1][j1] -= colk[i1] * Aug[k][j1];
        }
        __syncthreads();
    }

    // Ks transposed: St[n][j] = sf2 * exp(-0.5 (tq[j]-t[n])^2 / l2)
    for (int idx = tid; idx < Tt * Nn; idx += 256) {
        int j = idx >> 4, n = idx & 15;
        float d = tq[j] - tt[n];
        St[n][j] = SF2 * __expf(NEG_HALF_INV_L2 * d * d);
    }
    __syncthreads();

    // U[i][n] = sum_m Ks[i][m] * Kinv[m][n]
    for (int idx = tid; idx < Tt * Nn; idx += 256) {
        int i = idx >> 4, n = idx & 15;
        float s = 0.0f;
        #pragma unroll
        for (int m = 0; m < Nn; m++) s += St[m][i] * Aug[m][Nn + n];
        U[i][n] = s;
    }
    __syncthreads();

    // mu[a][i] = sum_n U[i][n] * y[a][n]
    for (int idx = tid; idx < Aa * Tt; idx += 256) {
        int a = idx >> 7, i = idx & 127;
        float s = 0.0f;
        #pragma unroll
        for (int n = 0; n < Nn; n++) s += U[i][n] * ys[a][n];
        out_mu[((size_t)e * Aa + a) * Tt + i] = s;
    }

    // cov[i][j] = kssd[|i-j|] - dot16(U[i], Ks[j]); written 8x (one per anchor)
    const int lane = tid & 31;
    const int grp  = tid >> 5;
    const int j0   = lane * 4;
    for (int step = 0; step < Tt / 8; step++) {
        int i = step * 8 + grp;
        float u[Nn];
        #pragma unroll
        for (int n = 0; n < Nn; n++) u[n] = U[i][n];   // broadcast LDS
        float a0 = 0.f, a1 = 0.f, a2 = 0.f, a3 = 0.f;
        #pragma unroll
        for (int n = 0; n < Nn; n++) {
            float4 s4 = *(const float4*)&St[n][j0];    // conflict-free LDS.128
            float un = u[n];
            a0 += un * s4.x; a1 += un * s4.y; a2 += un * s4.z; a3 += un * s4.w;
        }
        int d0 = i - j0;       d0 = d0 < 0 ? -d0 : d0;
        int d1 = i - (j0 + 1); d1 = d1 < 0 ? -d1 : d1;
        int d2 = i - (j0 + 2); d2 = d2 < 0 ? -d2 : d2;
        int d3 = i - (j0 + 3); d3 = d3 < 0 ? -d3 : d3;
        float4 v;
        v.x = kssd[d0] - a0;
        v.y = kssd[d1] - a1;
        v.z = kssd[d2] - a2;
        v.w = kssd[d3] - a3;
        size_t base = (((size_t)e * Aa) * Tt + i) * Tt + j0;
        #pragma unroll
        for (int a = 0; a < Aa; a++) {
            *(float4*)&out_cov[base + (size_t)a * Tt * Tt] = v;   // coalesced STG.128
        }
    }
}

// ---------------------------------------------------------------------------
extern "C" void kernel_launch(void* const* d_in, const int* in_sizes, int n_in,
                              void* d_out, int out_size)
{
    const float* x  = (const float*)d_in[0];
    // d_in[1] = a, d_in[2] = da (unused by reference)
    const float* W1 = (const float*)d_in[3];
    const float* b1 = (const float*)d_in[4];
    const float* W2 = (const float*)d_in[5];
    const float* b2 = (const float*)d_in[6];
    const float* Wt = (const float*)d_in[7];
    const float* bt = (const float*)d_in[8];
    const float* Wa = (const float*)d_in[9];
    const float* ba = (const float*)d_in[10];
    const float* tq = (const float*)d_in[11];

    float* out     = (float*)d_out;
    float* out_mu  = out;                                   // E*A*T floats
    float* out_cov = out + (size_t)E_TOT * Aa * Tt;         // E*A*T*T floats

    float* h1 = nullptr; float* h2 = nullptr; float* hd = nullptr;
    cudaGetSymbolAddress((void**)&h1, g_h1);
    cudaGetSymbolAddress((void**)&h2, g_h2);
    cudaGetSymbolAddress((void**)&hd, g_head);

    // layer 1: [512,256] = tanh(x @ W1^T + b1), k=64
    gemm_kernel<32, 64, 256, Dd, true, false>
        <<<dim3(E_TOT / 32, Hh / 64), 256>>>(x, W1, nullptr, b1, nullptr, h1, Hh);
    // layer 2: [512,256] = tanh(h1 @ W2^T + b2), k=256
    gemm_kernel<32, 32, 128, Hh, true, false>
        <<<dim3(E_TOT / 32, Hh / 32), 128>>>(h1, W2, nullptr, b2, nullptr, h2, Hh);
    // heads: [512,144] = h2 @ [Wt;Wa]^T + [bt;ba], k=256
    gemm_kernel<32, 48, 192, Hh, false, true>
        <<<dim3(E_TOT / 32, HO / 48), 192>>>(h2, Wt, Wa, bt, ba, hd, HO);

    gp_kernel<<<E_TOT, 256>>>(tq, out_mu, out_cov);
}

// round 7
// speedup vs baseline: 1.5163x; 1.4699x over previous
#include <cuda_runtime.h>
#include <cuda_bf16.h>
#include <cstddef>

#define E_TOT 512
#define Dd    64
#define Hh    256
#define Nn    16
#define Aa    8
#define Tt    128
#define HO    (Nn + Aa * Nn)   // 144 head outputs

#define SF2   0.01f
#define SN2   0.01f
#define NEG_HALF_INV_L2 (-50.0f)   // -0.5 / 0.1^2

// scratch (no allocation allowed -> device globals)
__device__ float g_h1[E_TOT * Hh];     // layer-1 activations
__device__ float g_h2[E_TOT * Hh];     // layer-2 activations
__device__ float g_head[E_TOT * HO];   // [times(16) | anchors(128)] per e

// ---------------------------------------------------------------------------
// Tiled GEMM, sized for warp-parallelism: BM=16 e-rows, BN cols, 256 threads.
//   grid = (E/16, OUTC/BN) -> 256-288 blocks, ~2 blocks/SM, ~4 warps/SMSP.
//   C[row][col] = act( A[row][:] . W[col][:] + bias[col] )
//   Inner loop: 2 LDS (1 broadcast pair + 1 broadcast) + RPT FFMA per k.
// ---------------------------------------------------------------------------
template<int BN, int KTOT, bool DOTANH, bool SPLITW>
__global__ __launch_bounds__(256)
void gemm_kernel(const float* __restrict__ A,
                 const float* __restrict__ W,    // or Wt when SPLITW
                 const float* __restrict__ Wb,   // Wa when SPLITW
                 const float* __restrict__ bias,    // or bt
                 const float* __restrict__ biasb,   // ba when SPLITW
                 float* __restrict__ C, int OUTC)
{
    constexpr int BM  = 16;
    constexpr int RPT = (BM * BN) / 256;    // rows per thread: 2 (BN=32), 1 (BN=16)
    __shared__ float Ash[64][BM + 2];       // stride 18 (even): LDS.64-able pairs
    __shared__ float Bsh[64][BN + 1];       // odd stride: conflict-free

    const int tid  = threadIdx.x;
    const int c    = tid % BN;              // col within tile (lane-fast -> bcast/cf)
    const int rg   = tid / BN;              // row group
    const int row0 = blockIdx.x * BM;
    const int col0 = blockIdx.y * BN;

    float acc[RPT];
    #pragma unroll
    for (int r = 0; r < RPT; r++) acc[r] = 0.0f;

    for (int k0 = 0; k0 < KTOT; k0 += 64) {
        // stage A tile: 1024 elems, coalesced (kk fast)
        #pragma unroll
        for (int i = tid; i < BM * 64; i += 256) {
            int r = i >> 6, kk = i & 63;
            Ash[kk][r] = A[(row0 + r) * KTOT + k0 + kk];
        }
        // stage W tile: BN*64 elems, coalesced
        #pragma unroll
        for (int i = tid; i < BN * 64; i += 256) {
            int cc = i >> 6, kk = i & 63;
            int cg = col0 + cc;
            float v;
            if (SPLITW) v = (cg < Nn) ? W[cg * KTOT + k0 + kk]
                                      : Wb[(cg - Nn) * KTOT + k0 + kk];
            else        v = W[cg * KTOT + k0 + kk];
            Bsh[kk][cc] = v;
        }
        __syncthreads();

        #pragma unroll 16
        for (int kk = 0; kk < 64; kk++) {
            float b = Bsh[kk][c];
            #pragma unroll
            for (int r = 0; r < RPT; r++)
                acc[r] += Ash[kk][rg * RPT + r] * b;
        }
        __syncthreads();
    }

    #pragma unroll
    for (int r = 0; r < RPT; r++) {
        int row = row0 + rg * RPT + r;
        int col = col0 + c;
        float bv;
        if (SPLITW) bv = (col < Nn) ? bias[col] : biasb[col - Nn];
        else        bv = bias[col];
        float v = acc[r] + bv;
        if (DOTANH) v = tanhf(v);
        C[row * OUTC + col] = v;
    }
}

// ---------------------------------------------------------------------------
// GP per environment e. 512 blocks, 256 threads.  (R1 exact, proven ~51us)
// ---------------------------------------------------------------------------
__global__ __launch_bounds__(256)
void gp_kernel(const float* __restrict__ tq_g,
               float* __restrict__ out_mu,
               float* __restrict__ out_cov)
{
    __shared__ float tq[Tt];
    __shared__ float kssd[Tt];               // Kss[i][j] == kssd[|i-j|]
    __shared__ float tt[Nn];
    __shared__ float ys[Aa][Nn];
    __shared__ float Aug[Nn][2 * Nn + 1];    // [K | I] -> [I | K^-1], pad 33
    __shared__ float colk[Nn];
    __shared__ float St[Nn][Tt + 4];         // Ks transposed: St[n][j], pad 132
    __shared__ float U[Tt][Nn + 1];          // U = Ks @ K^-1, pad 17

    const int e   = blockIdx.x;
    const int tid = threadIdx.x;

    if (tid < Tt) tq[tid] = tq_g[tid];
    if (tid < Nn) tt[tid] = g_head[e * HO + tid];
    if (tid >= 128 && tid < 128 + Aa * Nn) {
        int q = tid - 128;
        ys[q >> 4][q & 15] = g_head[e * HO + Nn + q];
    }
    __syncthreads();

    if (tid < Tt) {
        float d = tq[tid] - tq[0];
        kssd[tid] = SF2 * __expf(NEG_HALF_INV_L2 * d * d);
    }
    // build [K + sn2 I | I]  (exactly 256 entries of K)
    {
        int i = tid >> 4, j = tid & 15;
        float d = tt[i] - tt[j];
        float v = SF2 * __expf(NEG_HALF_INV_L2 * d * d);
        if (i == j) v += SN2;
        Aug[i][j] = v;
        Aug[i][Nn + j] = (i == j) ? 1.0f : 0.0f;
    }
    __syncthreads();

    // Gauss-Jordan (SPD, no pivoting needed, cond(K) <= 17)
    for (int k = 0; k < Nn; k++) {
        float pinv = 1.0f / Aug[k][k];
        __syncthreads();
        if (tid < 32) Aug[k][tid] *= pinv;
        if (tid >= 32 && tid < 48) colk[tid - 32] = Aug[tid - 32][k];
        __syncthreads();
        {
            int idx = tid;            // 512 elements, 256 threads, 2 each
            int i0 = idx >> 5, j0 = idx & 31;
            if (i0 != k) Aug[i0][j0] -= colk[i0] * Aug[k][j0];
            idx += 256;
            int i1 = idx >> 5, j1 = idx & 31;
            if (i1 != k) Aug[i1][j1] -= colk[i1] * Aug[k][j1];
        }
        __syncthreads();
    }

    // Ks transposed: St[n][j] = sf2 * exp(-0.5 (tq[j]-t[n])^2 / l2)
    for (int idx = tid; idx < Tt * Nn; idx += 256) {
        int j = idx >> 4, n = idx & 15;
        float d = tq[j] - tt[n];
        St[n][j] = SF2 * __expf(NEG_HALF_INV_L2 * d * d);
    }
    __syncthreads();

    // U[i][n] = sum_m Ks[i][m] * Kinv[m][n]
    for (int idx = tid; idx < Tt * Nn; idx += 256) {
        int i = idx >> 4, n = idx & 15;
        float s = 0.0f;
        #pragma unroll
        for (int m = 0; m < Nn; m++) s += St[m][i] * Aug[m][Nn + n];
        U[i][n] = s;
    }
    __syncthreads();

    // mu[a][i] = sum_n U[i][n] * y[a][n]
    for (int idx = tid; idx < Aa * Tt; idx += 256) {
        int a = idx >> 7, i = idx & 127;
        float s = 0.0f;
        #pragma unroll
        for (int n = 0; n < Nn; n++) s += U[i][n] * ys[a][n];
        out_mu[((size_t)e * Aa + a) * Tt + i] = s;
    }

    // cov[i][j] = kssd[|i-j|] - dot16(U[i], Ks[j]); written 8x (one per anchor)
    const int lane = tid & 31;
    const int grp  = tid >> 5;
    const int j0   = lane * 4;
    for (int step = 0; step < Tt / 8; step++) {
        int i = step * 8 + grp;
        float u[Nn];
        #pragma unroll
        for (int n = 0; n < Nn; n++) u[n] = U[i][n];   // broadcast LDS
        float a0 = 0.f, a1 = 0.f, a2 = 0.f, a3 = 0.f;
        #pragma unroll
        for (int n = 0; n < Nn; n++) {
            float4 s4 = *(const float4*)&St[n][j0];    // conflict-free LDS.128
            float un = u[n];
            a0 += un * s4.x; a1 += un * s4.y; a2 += un * s4.z; a3 += un * s4.w;
        }
        int d0 = i - j0;       d0 = d0 < 0 ? -d0 : d0;
        int d1 = i - (j0 + 1); d1 = d1 < 0 ? -d1 : d1;
        int d2 = i - (j0 + 2); d2 = d2 < 0 ? -d2 : d2;
        int d3 = i - (j0 + 3); d3 = d3 < 0 ? -d3 : d3;
        float4 v;
        v.x = kssd[d0] - a0;
        v.y = kssd[d1] - a1;
        v.z = kssd[d2] - a2;
        v.w = kssd[d3] - a3;
        size_t base = (((size_t)e * Aa) * Tt + i) * Tt + j0;
        #pragma unroll
        for (int a = 0; a < Aa; a++) {
            *(float4*)&out_cov[base + (size_t)a * Tt * Tt] = v;   // coalesced STG.128
        }
    }
}

// ---------------------------------------------------------------------------
extern "C" void kernel_launch(void* const* d_in, const int* in_sizes, int n_in,
                              void* d_out, int out_size)
{
    const float* x  = (const float*)d_in[0];
    // d_in[1] = a, d_in[2] = da (unused by reference)
    const float* W1 = (const float*)d_in[3];
    const float* b1 = (const float*)d_in[4];
    const float* W2 = (const float*)d_in[5];
    const float* b2 = (const float*)d_in[6];
    const float* Wt = (const float*)d_in[7];
    const float* bt = (const float*)d_in[8];
    const float* Wa = (const float*)d_in[9];
    const float* ba = (const float*)d_in[10];
    const float* tq = (const float*)d_in[11];

    float* out     = (float*)d_out;
    float* out_mu  = out;                                   // E*A*T floats
    float* out_cov = out + (size_t)E_TOT * Aa * Tt;         // E*A*T*T floats

    float* h1 = nullptr; float* h2 = nullptr; float* hd = nullptr;
    cudaGetSymbolAddress((void**)&h1, g_h1);
    cudaGetSymbolAddress((void**)&h2, g_h2);
    cudaGetSymbolAddress((void**)&hd, g_head);

    // layer 1: [512,256] = tanh(x @ W1^T + b1), k=64    -> 256 blocks
    gemm_kernel<32, Dd, true, false>
        <<<dim3(E_TOT / 16, Hh / 32), 256>>>(x, W1, nullptr, b1, nullptr, h1, Hh);
    // layer 2: [512,256] = tanh(h1 @ W2^T + b2), k=256  -> 256 blocks
    gemm_kernel<32, Hh, true, false>
        <<<dim3(E_TOT / 16, Hh / 32), 256>>>(h1, W2, nullptr, b2, nullptr, h2, Hh);
    // heads: [512,144] = h2 @ [Wt;Wa]^T + [bt;ba], k=256 -> 288 blocks
    gemm_kernel<16, Hh, false, true>
        <<<dim3(E_TOT / 16, HO / 16), 256>>>(h2, Wt, Wa, bt, ba, hd, HO);

    gp_kernel<<<E_TOT, 256>>>(tq, out_mu, out_cov);
}